// round 15
// baseline (speedup 1.0000x reference)
#include <cuda_runtime.h>
#include <cuda_fp16.h>

// Problem constants (fixed by the dataset's reference_code)
#define HW_DIM     512
#define NB         6
#define NLOOPS     4
#define NDET       4096
#define NSAMP      128
#define NBATCH     4
#define NPTS       (NDET * NSAMP)          // 524288
#define PIX        (512 * 512)             // per-channel elements
#define B_STRIDE   (2 * NB * PIX)          // per-batch elements (12 channels)

// Pixel-major packed refinement: g_pix[b][pix][k] = half2(x,y), 25.2 MB.
// A pixel's 6 buckets are contiguous (24 B). For even k0 the two taps
// (k0, k0+1) form an 8B-aligned uint2 -> ONE LDG.64 instead of two LDG.32.
__device__ __align__(16) unsigned g_pix[(long)NBATCH * PIX * NB];

static __device__ __forceinline__ unsigned pack_h2(float a, float b)
{
    __half2 h = __floats2half2_rn(a, b);
    return *reinterpret_cast<unsigned*>(&h);
}

// ---------------------------------------------------------------------------
// Repack: [B,12,H,W] f32 -> [B,PIX,6] half2. 75 MB total traffic, fully
// coalesced both sides via a 6 KB smem transpose tile (256 pixels x 6 words).
// Proven at ~6 us warm.
// ---------------------------------------------------------------------------
__global__ void __launch_bounds__(256)
repack_kernel(const float* __restrict__ refinement)
{
    __shared__ unsigned sm[256 * NB];        // 6 KB, pixel-major [p][k]

    const int b    = blockIdx.x >> 10;       // PIX/256 = 1024 tiles per batch
    const int base = (blockIdx.x & 1023) * 256;
    const int tid  = threadIdx.x;

    const float* rb = refinement + (long)b * B_STRIDE + base + tid;

    #pragma unroll
    for (int k = 0; k < NB; ++k) {
        const float xv = rb[(long)(2 * k)     * PIX];
        const float yv = rb[(long)(2 * k + 1) * PIX];
        sm[tid * NB + k] = pack_h2(xv, yv);
    }
    __syncthreads();

    uint2* dst = reinterpret_cast<uint2*>(g_pix + ((long)b * PIX + base) * NB);
    const uint2* src = reinterpret_cast<const uint2*>(sm);
    #pragma unroll
    for (int i = 0; i < 3; ++i)
        dst[tid + 256 * i] = src[tid + 256 * i];
}

// ---------------------------------------------------------------------------
// Refine: per iteration, even k0 -> ONE aligned 8B gather (both taps);
// odd k0 -> two 4B gathers in the same 24B block (2nd mostly L1-hit).
// ILP=1, exact fixed-point + 2-cycle early exits.
// ---------------------------------------------------------------------------
__global__ void __launch_bounds__(256)
refine_kernel(const float*  __restrict__ det_in,     // [NDET, NSAMP, 2]
              const float*  __restrict__ sampling,   // [NSAMP]
              const int*    __restrict__ bvec,       // [NDET]
              float*        __restrict__ out)        // [NDET, NSAMP, 2]
{
    const int t = blockIdx.x * blockDim.x + threadIdx.x;  // grid exact

    const int s = t & (NSAMP - 1);
    const int d = t >> 7;

    // Per-sample bucket setup — reproduce reference arithmetic exactly.
    const float base = sampling[s] * (float)NB;
    const float bif  = floorf(base);
    const int   bint = (int)bif;

    const float d0 = fabsf(bif - base);
    const float w0 = (d0 > 1.0f) ? 0.0f : (1.0f - d0);
    const float d1 = fabsf((bif + 1.0f) - base);
    const float w1 = (d1 > 1.0f) ? 0.0f : (1.0f - d1);

    const int  k0    = bint % NB;
    const int  k1    = (bint + 1) % NB;
    const bool evenK = (k0 & 1) == 0;        // loop-invariant per thread
    const unsigned* __restrict__ up = g_pix + (long)bvec[d] * PIX * NB;

    const float2 det = reinterpret_cast<const float2*>(det_in)[t];
    float x = det.x, y = det.y;
    float px = x,  py = y;                   // det_{l-1}

    int prev1 = -1, prev2 = -1;
    #pragma unroll
    for (int l = 0; l < NLOOPS; ++l) {
        float xr = rintf(x);                 // round-half-even == jnp.round
        float yr = rintf(y);
        xr = fminf(fmaxf(xr, 0.0f), (float)(HW_DIM - 1));
        yr = fminf(fmaxf(yr, 0.0f), (float)(HW_DIM - 1));
        const int pix = (int)yr * HW_DIM + (int)xr;

        if (pix == prev1) break;             // fixed point: det unchanged
        if (pix == prev2) {                  // 2-cycle: alternates forever
            if ((NLOOPS - l) & 1) { x = px; y = py; }
            break;
        }
        prev2 = prev1;  prev1 = pix;
        px = x;  py = y;

        const int o = pix * NB;
        unsigned va, vb;
        if (evenK) {
            // taps (k0, k0+1) are an aligned uint2 -> one LDG.64
            const uint2 v = __ldg(reinterpret_cast<const uint2*>(up + o + k0));
            va = v.x;  vb = v.y;
        } else {
            va = __ldg(up + o + k0);
            vb = __ldg(up + o + k1);
        }
        const float2 g0 = __half22float2(*reinterpret_cast<const __half2*>(&va));
        const float2 g1 = __half22float2(*reinterpret_cast<const __half2*>(&vb));

        x = xr + (w0 * g0.x + w1 * g1.x);
        y = yr + (w0 * g0.y + w1 * g1.y);
    }

    reinterpret_cast<float2*>(out)[t] = make_float2(x, y);
}

extern "C" void kernel_launch(void* const* d_in, const int* in_sizes, int n_in,
                              void* d_out, int out_size)
{
    // Identify inputs by element count:
    //   det_indices : 1048576 f32, refinement : 12582912 f32,
    //   sampling : 128 f32, b : 4096 i32
    const float* det_in     = nullptr;
    const float* refinement = nullptr;
    const float* sampling   = nullptr;
    const int*   bvec       = nullptr;

    for (int i = 0; i < n_in; ++i) {
        switch (in_sizes[i]) {
            case 1048576:  det_in     = (const float*)d_in[i]; break;
            case 12582912: refinement = (const float*)d_in[i]; break;
            case 128:      sampling   = (const float*)d_in[i]; break;
            case 4096:     bvec       = (const int*)d_in[i];   break;
            default: break;
        }
    }

    repack_kernel<<<NBATCH * (PIX / 256), 256>>>(refinement);   // 4096 blocks
    refine_kernel<<<NPTS / 256, 256>>>(det_in, sampling, bvec, (float*)d_out);
}